// round 11
// baseline (speedup 1.0000x reference)
#include <cuda_runtime.h>
#include <cuda_bf16.h>
#include <cstdint>

#define HID   2048
#define HD    128
#define NH    16
#define BATCH 2
#define SEQ   2048
#define MROWS (BATCH*SEQ)   // 4096

// Scratch (no allocation allowed -> __device__ globals)
__device__ float g_q[(size_t)MROWS * HID];
__device__ float g_k[(size_t)MROWS * HD];
__device__ float g_vt[(size_t)BATCH * HD * SEQ];   // V transposed: [b][d][s]
__device__ float g_o[(size_t)MROWS * HID];
__device__ float g_x[(size_t)MROWS * HID];   // tf32-rounded x
__device__ float g_wq[(size_t)HID * HID];    // tf32-rounded w_q
__device__ float g_wo[(size_t)HID * HID];    // tf32-rounded w_out

__device__ __forceinline__ uint32_t cvt_tf32(float x) {
    uint32_t r; asm("cvt.rna.tf32.f32 %0, %1;" : "=r"(r) : "f"(x)); return r;
}

__device__ __forceinline__ void mma_tf32(float* d, const uint32_t* a,
                                         const uint32_t* b, const float* c) {
    asm volatile(
        "mma.sync.aligned.m16n8k8.row.col.f32.tf32.tf32.f32 "
        "{%0,%1,%2,%3}, {%4,%5,%6,%7}, {%8,%9}, {%10,%11,%12,%13};"
        : "=f"(d[0]), "=f"(d[1]), "=f"(d[2]), "=f"(d[3])
        : "r"(a[0]), "r"(a[1]), "r"(a[2]), "r"(a[3]),
          "r"(b[0]), "r"(b[1]),
          "f"(c[0]), "f"(c[1]), "f"(c[2]), "f"(c[3]));
}

// ldmatrix x4: four 8x8-b16 tiles (= four 8x4 tiles of 32-bit words)
__device__ __forceinline__ void ldsm4(uint32_t& r0, uint32_t& r1,
                                      uint32_t& r2, uint32_t& r3, uint32_t addr) {
    asm volatile("ldmatrix.sync.aligned.m8n8.x4.shared.b16 {%0,%1,%2,%3}, [%4];"
                 : "=r"(r0), "=r"(r1), "=r"(r2), "=r"(r3) : "r"(addr));
}

__device__ __forceinline__ void cp16(uint32_t dst, const void* src) {
    asm volatile("cp.async.ca.shared.global [%0], [%1], 16;" :: "r"(dst), "l"(src));
}
#define CP_COMMIT() asm volatile("cp.async.commit_group;" ::: "memory")
#define CP_WAIT(n)  asm volatile("cp.async.wait_group %0;" :: "n"(n) : "memory")

__device__ __forceinline__ uint32_t smem_u32(const void* p) {
    uint32_t a;
    asm("{ .reg .u64 t; cvta.to.shared.u64 t, %1; cvt.u32.u64 %0, t; }"
        : "=r"(a) : "l"(p));
    return a;
}

// ===========================================================================
// Pre-pass: RNA-round three arrays to tf32
// ===========================================================================
__global__ void round3_tf32(const float* __restrict__ a, float* __restrict__ ao, int na4,
                            const float* __restrict__ b, float* __restrict__ bo, int nb4,
                            const float* __restrict__ c, float* __restrict__ co, int nc4)
{
    int total = na4 + nb4 + nc4;
    for (int i = blockIdx.x * blockDim.x + threadIdx.x; i < total;
         i += gridDim.x * blockDim.x) {
        const float4* src; float4* dst; int j = i;
        if (j < na4) { src = (const float4*)a; dst = (float4*)ao; }
        else if ((j -= na4) < nb4) { src = (const float4*)b; dst = (float4*)bo; }
        else { j -= nb4; src = (const float4*)c; dst = (float4*)co; }
        float4 v = src[j];
        v.x = __uint_as_float(cvt_tf32(v.x));
        v.y = __uint_as_float(cvt_tf32(v.y));
        v.z = __uint_as_float(cvt_tf32(v.z));
        v.w = __uint_as_float(cvt_tf32(v.w));
        dst[j] = v;
    }
}

// ===========================================================================
// Wide tf32 GEMM: C[M,N] = A[M,K]*B[N,K]^T, 128x256 CTA, cp.async, BK=32.
// ===========================================================================
#define WPAD  36
#define WASZ  (128 * WPAD)
#define WBSZ  (256 * WPAD)
#define WSTG  (WASZ + WBSZ)
#define WSMEM (2 * WSTG * 4)

__global__ __launch_bounds__(256, 1) void gemm_wide(
    const float* __restrict__ A, const float* __restrict__ B,
    float* __restrict__ C, int M, int N, int K, int round_out)
{
    extern __shared__ float smf[];
    const uint32_t sb = smem_u32(smf);
    const int tid  = threadIdx.x;
    const int wid  = tid >> 5;
    const int lane = tid & 31;
    const int grp  = lane >> 2;
    const int tg   = lane & 3;
    const int wm   = (wid & 1) * 64;
    const int wn   = (wid >> 1) * 64;
    const int m0 = blockIdx.y * 128;
    const int n0 = blockIdx.x * 256;

    float acc[4][8][4];
#pragma unroll
    for (int i = 0; i < 4; i++)
#pragma unroll
        for (int j = 0; j < 8; j++)
#pragma unroll
            for (int r = 0; r < 4; r++) acc[i][j][r] = 0.f;

    const int nch = K / 32;

    auto load_stage = [&](int c, int buf) {
        const int k0 = c * 32;
        const uint32_t base = sb + buf * WSTG * 4;
#pragma unroll
        for (int i = 0; i < 4; i++) {
            int g = tid + i * 256;
            int r = g >> 3, c4 = (g & 7) * 4;
            cp16(base + (r * WPAD + c4) * 4, &A[(size_t)(m0 + r) * K + k0 + c4]);
        }
#pragma unroll
        for (int i = 0; i < 8; i++) {
            int g = tid + i * 256;
            int r = g >> 3, c4 = (g & 7) * 4;
            cp16(base + (WASZ + r * WPAD + c4) * 4, &B[(size_t)(n0 + r) * K + k0 + c4]);
        }
        CP_COMMIT();
    };

    load_stage(0, 0);

    for (int c = 0; c < nch; c++) {
        CP_WAIT(0);
        __syncthreads();
        if (c + 1 < nch) load_stage(c + 1, (c + 1) & 1);

        const float* sA = smf + (c & 1) * WSTG;
        const float* sB = sA + WASZ;

#pragma unroll
        for (int ks = 0; ks < 4; ks++) {
            const int k0 = ks * 8;
            uint32_t afr[4][4], bfr[8][2];
#pragma unroll
            for (int mf = 0; mf < 4; mf++) {
                int row = wm + mf * 16 + grp;
                afr[mf][0] = __float_as_uint(sA[row * WPAD + k0 + tg]);
                afr[mf][1] = __float_as_uint(sA[(row + 8) * WPAD + k0 + tg]);
                afr[mf][2] = __float_as_uint(sA[row * WPAD + k0 + tg + 4]);
                afr[mf][3] = __float_as_uint(sA[(row + 8) * WPAD + k0 + tg + 4]);
            }
#pragma unroll
            for (int nf = 0; nf < 8; nf++) {
                int col = wn + nf * 8 + grp;
                bfr[nf][0] = __float_as_uint(sB[col * WPAD + k0 + tg]);
                bfr[nf][1] = __float_as_uint(sB[col * WPAD + k0 + tg + 4]);
            }
#pragma unroll
            for (int mf = 0; mf < 4; mf++)
#pragma unroll
                for (int nf = 0; nf < 8; nf++)
                    mma_tf32(acc[mf][nf], afr[mf], bfr[nf], acc[mf][nf]);
        }
    }

#pragma unroll
    for (int mf = 0; mf < 4; mf++) {
#pragma unroll
        for (int nf = 0; nf < 8; nf++) {
            int row = m0 + wm + mf * 16 + grp;
            int col = n0 + wn + nf * 8 + tg * 2;
            float v0 = acc[mf][nf][0], v1 = acc[mf][nf][1];
            float v2 = acc[mf][nf][2], v3 = acc[mf][nf][3];
            if (round_out) {
                v0 = __uint_as_float(cvt_tf32(v0));
                v1 = __uint_as_float(cvt_tf32(v1));
                v2 = __uint_as_float(cvt_tf32(v2));
                v3 = __uint_as_float(cvt_tf32(v3));
            }
            *(float2*)&C[(size_t)row * N + col] = make_float2(v0, v1);
            *(float2*)&C[(size_t)(row + 8) * N + col] = make_float2(v2, v3);
        }
    }
}

// ===========================================================================
// Small GEMM: K proj (z==0) normal; V proj (z==1) writes Vt transposed [b][d][s].
// ===========================================================================
#define BK   32
#define PAD  36

__global__ __launch_bounds__(256, 2) void gemm_kv(
    const float* __restrict__ A, const float* __restrict__ Bk,
    float* __restrict__ C, int M, int N, int K,
    const float* __restrict__ Bv, float* __restrict__ Vt)
{
    __shared__ uint32_t As[128 * PAD];
    __shared__ uint32_t Bs[128 * PAD];

    const float* B = (blockIdx.z == 1) ? Bv : Bk;

    const int tid  = threadIdx.x;
    const int wid  = tid >> 5;
    const int lane = tid & 31;
    const int grp  = lane >> 2;
    const int tg   = lane & 3;
    const int wm   = (wid & 1) * 64;
    const int wn   = (wid >> 1) * 32;
    const int m0 = blockIdx.y * 128;
    const int n0 = blockIdx.x * 128;

    const int ldr  = tid >> 3;
    const int ldc  = (tid & 7) * 4;

    float acc[4][4][4];
#pragma unroll
    for (int i = 0; i < 4; i++)
#pragma unroll
        for (int j = 0; j < 4; j++)
#pragma unroll
            for (int r = 0; r < 4; r++) acc[i][j][r] = 0.f;

    const int nchunks = K / BK;
    float4 pa[4], pb[4];

#pragma unroll
    for (int it = 0; it < 4; it++) {
        int r = ldr + it * 32;
        pa[it] = *(const float4*)&A[(size_t)(m0 + r) * K + ldc];
        pb[it] = *(const float4*)&B[(size_t)(n0 + r) * K + ldc];
    }

    for (int c = 0; c < nchunks; c++) {
#pragma unroll
        for (int it = 0; it < 4; it++) {
            int r = ldr + it * 32;
            As[r * PAD + ldc + 0] = cvt_tf32(pa[it].x);
            As[r * PAD + ldc + 1] = cvt_tf32(pa[it].y);
            As[r * PAD + ldc + 2] = cvt_tf32(pa[it].z);
            As[r * PAD + ldc + 3] = cvt_tf32(pa[it].w);
            Bs[r * PAD + ldc + 0] = cvt_tf32(pb[it].x);
            Bs[r * PAD + ldc + 1] = cvt_tf32(pb[it].y);
            Bs[r * PAD + ldc + 2] = cvt_tf32(pb[it].z);
            Bs[r * PAD + ldc + 3] = cvt_tf32(pb[it].w);
        }
        __syncthreads();

        if (c + 1 < nchunks) {
            const int k0 = (c + 1) * BK;
#pragma unroll
            for (int it = 0; it < 4; it++) {
                int r = ldr + it * 32;
                pa[it] = *(const float4*)&A[(size_t)(m0 + r) * K + k0 + ldc];
                pb[it] = *(const float4*)&B[(size_t)(n0 + r) * K + k0 + ldc];
            }
        }

#pragma unroll
        for (int ks = 0; ks < 4; ks++) {
            const int k0 = ks * 8;
            uint32_t afr[4][4], bfr[4][2];
#pragma unroll
            for (int mf = 0; mf < 4; mf++) {
                int row = wm + mf * 16 + grp;
                afr[mf][0] = As[row * PAD + k0 + tg];
                afr[mf][1] = As[(row + 8) * PAD + k0 + tg];
                afr[mf][2] = As[row * PAD + k0 + tg + 4];
                afr[mf][3] = As[(row + 8) * PAD + k0 + tg + 4];
            }
#pragma unroll
            for (int nf = 0; nf < 4; nf++) {
                int col = wn + nf * 8 + grp;
                bfr[nf][0] = Bs[col * PAD + k0 + tg];
                bfr[nf][1] = Bs[col * PAD + k0 + tg + 4];
            }
#pragma unroll
            for (int mf = 0; mf < 4; mf++)
#pragma unroll
                for (int nf = 0; nf < 4; nf++)
                    mma_tf32(acc[mf][nf], afr[mf], bfr[nf], acc[mf][nf]);
        }
        __syncthreads();
    }

#pragma unroll
    for (int mf = 0; mf < 4; mf++) {
#pragma unroll
        for (int nf = 0; nf < 4; nf++) {
            int row = m0 + wm + mf * 16 + grp;
            int col = n0 + wn + nf * 8 + tg * 2;
            float v0 = __uint_as_float(cvt_tf32(acc[mf][nf][0]));
            float v1 = __uint_as_float(cvt_tf32(acc[mf][nf][1]));
            float v2 = __uint_as_float(cvt_tf32(acc[mf][nf][2]));
            float v3 = __uint_as_float(cvt_tf32(acc[mf][nf][3]));
            if (blockIdx.z == 0) {
                *(float2*)&C[(size_t)row * N + col] = make_float2(v0, v1);
                *(float2*)&C[(size_t)(row + 8) * N + col] = make_float2(v2, v3);
            } else {
                int b = row >> 11, s = row & 2047;
                Vt[((size_t)b * HD + col) * SEQ + s]           = v0;
                Vt[((size_t)b * HD + col + 1) * SEQ + s]       = v1;
                Vt[((size_t)b * HD + col) * SEQ + s + 8]       = v2;
                Vt[((size_t)b * HD + col + 1) * SEQ + s + 8]   = v3;
            }
        }
    }
}

// ===========================================================================
// Tensor-core flash MQA (R8 structure: Q frags + P in regs, LDSM for K/V^T,
// quad-shuffle PV remap) at 128 threads / BQ=64 so TWO CTAs fit per SM:
// one CTA's MMAs hide the other's softmax latency.
// ===========================================================================
#define BQ    64
#define BKEY  64
#define PADK  132
#define PADVT 68
#define OFF_K0 0
#define OFF_K1 (64 * PADK)            // 8448
#define OFF_VT (2 * 64 * PADK)        // 16896
#define FLASH_SMEM ((OFF_VT + 128 * PADVT) * 4)   // 102400 B (x2 = 204.8 KB/SM)

__global__ __launch_bounds__(128, 2) void flash_mqa_tc(
    const float* __restrict__ Q, const float* __restrict__ Kg,
    const float* __restrict__ VTg, float* __restrict__ O)
{
    extern __shared__ float sm[];
    const uint32_t sb = smem_u32(sm);
    const int tid = threadIdx.x;
    const int wid = tid >> 5;       // 0..3
    const int lane = tid & 31;
    const int grp = lane >> 2;
    const int tg  = lane & 3;
    const int h = blockIdx.x & 15;
    const int b = blockIdx.x >> 4;
    const int q0 = blockIdx.y * BQ;
    const float scale = 0.08838834764831845f;   // 1/sqrt(128)

    const float* kb  = Kg + (size_t)b * SEQ * HD;
    const float* vtb = VTg + (size_t)b * HD * SEQ;
    const int nb = SEQ / BKEY;   // 32

    auto load_k = [&](int blk, uint32_t koff) {
        const float* src = kb + (size_t)blk * BKEY * HD;
#pragma unroll
        for (int it = 0; it < 16; it++) {
            int idx = tid + it * 128;          // 0..2047 granules
            int r = idx >> 5, ch = (idx & 31) * 4;
            cp16(sb + (koff + r * PADK + ch) * 4, src + (size_t)r * HD + ch);
        }
    };
    auto load_vt = [&](int blk) {
        const float* src = vtb + blk * BKEY;
#pragma unroll
        for (int it = 0; it < 16; it++) {
            int idx = tid + it * 128;          // 0..2047 granules
            int r = idx >> 4, ch = (idx & 15) * 4;
            cp16(sb + (OFF_VT + r * PADVT + ch) * 4, src + (size_t)r * SEQ + ch);
        }
    };

    // Q fragments in registers (tf32-valued in gmem)
    uint32_t qf[16][4];
    {
        const float* qbase = Q + (size_t)(b * SEQ + q0 + wid * 16) * HID + h * HD;
#pragma unroll
        for (int ks = 0; ks < 16; ks++) {
            qf[ks][0] = __float_as_uint(qbase[(size_t)grp * HID + ks * 8 + tg]);
            qf[ks][1] = __float_as_uint(qbase[(size_t)(grp + 8) * HID + ks * 8 + tg]);
            qf[ks][2] = __float_as_uint(qbase[(size_t)grp * HID + ks * 8 + tg + 4]);
            qf[ks][3] = __float_as_uint(qbase[(size_t)(grp + 8) * HID + ks * 8 + tg + 4]);
        }
    }

    float o[16][4];
#pragma unroll
    for (int i = 0; i < 16; i++)
#pragma unroll
        for (int j = 0; j < 4; j++) o[i][j] = 0.f;
    float m0r = -1e30f, m1r = -1e30f, l0 = 0.f, l1 = 0.f;

    load_k(0, OFF_K0); load_vt(0); CP_COMMIT();
    load_k(1, OFF_K1); CP_COMMIT();

    // ldmatrix lane geometry: tile = lane>>3, row-in-tile = lane&7
    const int lrow8 = ((lane >> 4) & 1) * 8 + (lane & 7);
    const int lcolh = ((lane >> 3) & 1) * 4;
    const int qsl  = (lane & ~3) | (tg >> 1);
    const int qsl2 = qsl + 2;

    for (int blk = 0; blk < nb; blk++) {
        CP_WAIT(1);
        __syncthreads();

        const uint32_t kOff = sb + ((blk & 1) ? OFF_K1 : OFF_K0) * 4;
        const uint32_t vOff = sb + OFF_VT * 4;

        // ---- S = Q * K^T : K fragments via ldmatrix.x4 (2 nt per LDSM) ----
        float s[8][4];
#pragma unroll
        for (int nt = 0; nt < 8; nt++)
#pragma unroll
            for (int j = 0; j < 4; j++) s[nt][j] = 0.f;

#pragma unroll
        for (int ks = 0; ks < 16; ks++) {
#pragma unroll
            for (int p = 0; p < 4; p++) {
                uint32_t b0, b1, b2, b3;
                uint32_t addr = kOff +
                    (uint32_t)(((p * 16 + lrow8) * PADK + ks * 8 + lcolh) * 4);
                ldsm4(b0, b1, b2, b3, addr);
                uint32_t bf0[2] = {b0, b1}, bf1[2] = {b2, b3};
                mma_tf32(s[2 * p],     qf[ks], bf0, s[2 * p]);
                mma_tf32(s[2 * p + 1], qf[ks], bf1, s[2 * p + 1]);
            }
        }

        // ---- online softmax; P tf32-rounded in place ----
        float ml0 = -1e30f, ml1 = -1e30f;
#pragma unroll
        for (int nt = 0; nt < 8; nt++) {
            ml0 = fmaxf(ml0, fmaxf(s[nt][0], s[nt][1]));
            ml1 = fmaxf(ml1, fmaxf(s[nt][2], s[nt][3]));
        }
        ml0 *= scale; ml1 *= scale;
#pragma unroll
        for (int off = 1; off < 4; off <<= 1) {
            ml0 = fmaxf(ml0, __shfl_xor_sync(0xffffffffu, ml0, off));
            ml1 = fmaxf(ml1, __shfl_xor_sync(0xffffffffu, ml1, off));
        }
        const float mn0 = fmaxf(m0r, ml0);
        const float mn1 = fmaxf(m1r, ml1);
        const float a0 = __expf(m0r - mn0);
        const float a1 = __expf(m1r - mn1);
        float sum0 = 0.f, sum1 = 0.f;
#pragma unroll
        for (int nt = 0; nt < 8; nt++) {
            float p00 = __expf(s[nt][0] * scale - mn0);
            float p01 = __expf(s[nt][1] * scale - mn0);
            float p10 = __expf(s[nt][2] * scale - mn1);
            float p11 = __expf(s[nt][3] * scale - mn1);
            sum0 += p00 + p01;
            sum1 += p10 + p11;
            s[nt][0] = __uint_as_float(cvt_tf32(p00));
            s[nt][1] = __uint_as_float(cvt_tf32(p01));
            s[nt][2] = __uint_as_float(cvt_tf32(p10));
            s[nt][3] = __uint_as_float(cvt_tf32(p11));
        }
#pragma unroll
        for (int off = 1; off < 4; off <<= 1) {
            sum0 += __shfl_xor_sync(0xffffffffu, sum0, off);
            sum1 += __shfl_xor_sync(0xffffffffu, sum1, off);
        }
        l0 = l0 * a0 + sum0;
        l1 = l1 * a1 + sum1;
        m0r = mn0; m1r = mn1;
#pragma unroll
        for (int nt = 0; nt < 16; nt++) {
            o[nt][0] *= a0; o[nt][1] *= a0;
            o[nt][2] *= a1; o[nt][3] *= a1;
        }

        // ---- O += P * V : A-frags from s via quad shuffles; V^T via LDSM ----
#pragma unroll
        for (int ks2 = 0; ks2 < 8; ks2++) {
            float e0, e1;
            uint32_t af[4];
            e0 = __shfl_sync(0xffffffffu, s[ks2][0], qsl);
            e1 = __shfl_sync(0xffffffffu, s[ks2][1], qsl);
            af[0] = __float_as_uint((tg & 1) ? e1 : e0);
            e0 = __shfl_sync(0xffffffffu, s[ks2][2], qsl);
            e1 = __shfl_sync(0xffffffffu, s[ks2][3], qsl);
            af[1] = __float_as_uint((tg & 1) ? e1 : e0);
            e0 = __shfl_sync(0xffffffffu, s[ks2][0], qsl2);
            e1 = __shfl_sync(0xffffffffu, s[ks2][1], qsl2);
            af[2] = __float_as_uint((tg & 1) ? e1 : e0);
            e0 = __shfl_sync(0xffffffffu, s[ks2][2], qsl2);
            e1 = __shfl_sync(0xffffffffu, s[ks2][3], qsl2);
            af[3] = __float_as_uint((tg & 1) ? e1 : e0);
#pragma unroll
            for (int p = 0; p < 8; p++) {
                uint32_t b0, b1, b2, b3;
                uint32_t addr = vOff +
                    (uint32_t)(((p * 16 + lrow8) * PADVT + ks2 * 8 + lcolh) * 4);
                ldsm4(b0, b1, b2, b3, addr);
                uint32_t bf0[2] = {b0, b1}, bf1[2] = {b2, b3};
                mma_tf32(o[2 * p],     af, bf0, o[2 * p]);
                mma_tf32(o[2 * p + 1], af, bf1, o[2 * p + 1]);
            }
        }
        __syncthreads();

        if (blk + 1 < nb) load_vt(blk + 1);
        CP_COMMIT();
        if (blk + 2 < nb) load_k(blk + 2, (blk & 1) ? OFF_K1 : OFF_K0);
        CP_COMMIT();
    }

    // ---- epilogue (tf32-rounded for out-projection path) ----
    const float inv0 = 1.f / l0;
    const float inv1 = 1.f / l1;
    float* ob = O + (size_t)(b * SEQ + q0 + wid * 16) * HID + h * HD;
#pragma unroll
    for (int nt = 0; nt < 16; nt++) {
        int c = nt * 8 + 2 * tg;
        float v0 = __uint_as_float(cvt_tf32(o[nt][0] * inv0));
        float v1 = __uint_as_float(cvt_tf32(o[nt][1] * inv0));
        float v2 = __uint_as_float(cvt_tf32(o[nt][2] * inv1));
        float v3 = __uint_as_float(cvt_tf32(o[nt][3] * inv1));
        *(float2*)&ob[(size_t)grp * HID + c] = make_float2(v0, v1);
        *(float2*)&ob[(size_t)(grp + 8) * HID + c] = make_float2(v2, v3);
    }
}

// ===========================================================================
extern "C" void kernel_launch(void* const* d_in, const int* in_sizes, int n_in,
                              void* d_out, int out_size)
{
    const float* x  = (const float*)d_in[0];
    const float* wq = (const float*)d_in[1];
    const float* wk = (const float*)d_in[2];
    const float* wv = (const float*)d_in[3];
    const float* wo = (const float*)d_in[4];
    float* out = (float*)d_out;

    float *q, *k, *vt, *o, *xr, *wqr, *wor;
    cudaGetSymbolAddress((void**)&q, g_q);
    cudaGetSymbolAddress((void**)&k, g_k);
    cudaGetSymbolAddress((void**)&vt, g_vt);
    cudaGetSymbolAddress((void**)&o, g_o);
    cudaGetSymbolAddress((void**)&xr, g_x);
    cudaGetSymbolAddress((void**)&wqr, g_wq);
    cudaGetSymbolAddress((void**)&wor, g_wo);

    cudaFuncSetAttribute(flash_mqa_tc,
                         cudaFuncAttributeMaxDynamicSharedMemorySize, FLASH_SMEM);
    cudaFuncSetAttribute(gemm_wide,
                         cudaFuncAttributeMaxDynamicSharedMemorySize, WSMEM);

    // Round x, w_q, w_out to tf32
    round3_tf32<<<2048, 256>>>(x, xr, MROWS * HID / 4,
                               wq, wqr, HID * HID / 4,
                               wo, wor, HID * HID / 4);

    // Q projection (wide tensor GEMM, tf32-rounded output)
    gemm_wide<<<dim3(HID / 256, MROWS / 128), 256, WSMEM>>>(
        xr, wqr, q, MROWS, HID, HID, 1);

    // K (normal) and V (transposed) projections fused
    gemm_kv<<<dim3(HD / 128, MROWS / 128, 2), 256>>>(
        x, wk, k, MROWS, HD, HID, wv, vt);

    // Tensor-core flash attention: 128-thread CTAs, 2 CTAs/SM
    flash_mqa_tc<<<dim3(BATCH * NH, SEQ / BQ), 128, FLASH_SMEM>>>(q, k, vt, o);

    // Output projection (wide tensor GEMM, full fp32 output)
    gemm_wide<<<dim3(HID / 256, MROWS / 128), 256, WSMEM>>>(
        o, wor, out, MROWS, HID, HID, 0);
}

// round 13
// speedup vs baseline: 1.4435x; 1.4435x over previous
#include <cuda_runtime.h>
#include <cuda_fp16.h>
#include <cstdint>

#define HID   2048
#define HD    128
#define NH    16
#define BATCH 2
#define SEQ   2048
#define MROWS (BATCH*SEQ)   // 4096

// Scratch (no allocation allowed -> __device__ globals)
__device__ __half g_qh[(size_t)MROWS * HID];        // Q fp16
__device__ __half g_kh[(size_t)MROWS * HD];         // K fp16 [b,s,d]
__device__ __half g_vth[(size_t)BATCH * HD * SEQ];  // V^T fp16 [b,d,s]
__device__ float  g_o[(size_t)MROWS * HID];
__device__ float  g_x[(size_t)MROWS * HID];         // tf32-rounded x
__device__ float  g_wq[(size_t)HID * HID];          // tf32-rounded w_q
__device__ float  g_wo[(size_t)HID * HID];          // tf32-rounded w_out

__device__ __forceinline__ uint32_t cvt_tf32(float x) {
    uint32_t r; asm("cvt.rna.tf32.f32 %0, %1;" : "=r"(r) : "f"(x)); return r;
}

__device__ __forceinline__ void mma_tf32(float* d, const uint32_t* a,
                                         const uint32_t* b, const float* c) {
    asm volatile(
        "mma.sync.aligned.m16n8k8.row.col.f32.tf32.tf32.f32 "
        "{%0,%1,%2,%3}, {%4,%5,%6,%7}, {%8,%9}, {%10,%11,%12,%13};"
        : "=f"(d[0]), "=f"(d[1]), "=f"(d[2]), "=f"(d[3])
        : "r"(a[0]), "r"(a[1]), "r"(a[2]), "r"(a[3]),
          "r"(b[0]), "r"(b[1]),
          "f"(c[0]), "f"(c[1]), "f"(c[2]), "f"(c[3]));
}

__device__ __forceinline__ void mma_f16(float* d, const uint32_t* a,
                                        const uint32_t* b, const float* c) {
    asm volatile(
        "mma.sync.aligned.m16n8k16.row.col.f32.f16.f16.f32 "
        "{%0,%1,%2,%3}, {%4,%5,%6,%7}, {%8,%9}, {%10,%11,%12,%13};"
        : "=f"(d[0]), "=f"(d[1]), "=f"(d[2]), "=f"(d[3])
        : "r"(a[0]), "r"(a[1]), "r"(a[2]), "r"(a[3]),
          "r"(b[0]), "r"(b[1]),
          "f"(c[0]), "f"(c[1]), "f"(c[2]), "f"(c[3]));
}

__device__ __forceinline__ void ldsm4(uint32_t& r0, uint32_t& r1,
                                      uint32_t& r2, uint32_t& r3, uint32_t addr) {
    asm volatile("ldmatrix.sync.aligned.m8n8.x4.shared.b16 {%0,%1,%2,%3}, [%4];"
                 : "=r"(r0), "=r"(r1), "=r"(r2), "=r"(r3) : "r"(addr));
}

__device__ __forceinline__ void cp16(uint32_t dst, const void* src) {
    asm volatile("cp.async.ca.shared.global [%0], [%1], 16;" :: "r"(dst), "l"(src));
}
#define CP_COMMIT() asm volatile("cp.async.commit_group;" ::: "memory")
#define CP_WAIT(n)  asm volatile("cp.async.wait_group %0;" :: "n"(n) : "memory")

__device__ __forceinline__ uint32_t smem_u32(const void* p) {
    uint32_t a;
    asm("{ .reg .u64 t; cvta.to.shared.u64 t, %1; cvt.u32.u64 %0, t; }"
        : "=r"(a) : "l"(p));
    return a;
}

__device__ __forceinline__ uint32_t pack_h2(float lo, float hi) {
    __half2 h = __floats2half2_rn(lo, hi);
    return *reinterpret_cast<uint32_t*>(&h);
}

// ===========================================================================
// Pre-pass: RNA-round three arrays to tf32
// ===========================================================================
__global__ void round3_tf32(const float* __restrict__ a, float* __restrict__ ao, int na4,
                            const float* __restrict__ b, float* __restrict__ bo, int nb4,
                            const float* __restrict__ c, float* __restrict__ co, int nc4)
{
    int total = na4 + nb4 + nc4;
    for (int i = blockIdx.x * blockDim.x + threadIdx.x; i < total;
         i += gridDim.x * blockDim.x) {
        const float4* src; float4* dst; int j = i;
        if (j < na4) { src = (const float4*)a; dst = (float4*)ao; }
        else if ((j -= na4) < nb4) { src = (const float4*)b; dst = (float4*)bo; }
        else { j -= nb4; src = (const float4*)c; dst = (float4*)co; }
        float4 v = src[j];
        v.x = __uint_as_float(cvt_tf32(v.x));
        v.y = __uint_as_float(cvt_tf32(v.y));
        v.z = __uint_as_float(cvt_tf32(v.z));
        v.w = __uint_as_float(cvt_tf32(v.w));
        dst[j] = v;
    }
}

// ===========================================================================
// Wide tf32 GEMM: C = A*B^T, 128x256 CTA. mode 0: fp32 out; mode 2: fp16 out.
// ===========================================================================
#define WPAD  36
#define WASZ  (128 * WPAD)
#define WBSZ  (256 * WPAD)
#define WSTG  (WASZ + WBSZ)
#define WSMEM (2 * WSTG * 4)

__global__ __launch_bounds__(256, 1) void gemm_wide(
    const float* __restrict__ A, const float* __restrict__ B,
    float* __restrict__ C, __half* __restrict__ Ch,
    int M, int N, int K, int mode)
{
    extern __shared__ float smf[];
    const uint32_t sb = smem_u32(smf);
    const int tid  = threadIdx.x;
    const int wid  = tid >> 5;
    const int lane = tid & 31;
    const int grp  = lane >> 2;
    const int tg   = lane & 3;
    const int wm   = (wid & 1) * 64;
    const int wn   = (wid >> 1) * 64;
    const int m0 = blockIdx.y * 128;
    const int n0 = blockIdx.x * 256;

    float acc[4][8][4];
#pragma unroll
    for (int i = 0; i < 4; i++)
#pragma unroll
        for (int j = 0; j < 8; j++)
#pragma unroll
            for (int r = 0; r < 4; r++) acc[i][j][r] = 0.f;

    const int nch = K / 32;

    auto load_stage = [&](int c, int buf) {
        const int k0 = c * 32;
        const uint32_t base = sb + buf * WSTG * 4;
#pragma unroll
        for (int i = 0; i < 4; i++) {
            int g = tid + i * 256;
            int r = g >> 3, c4 = (g & 7) * 4;
            cp16(base + (r * WPAD + c4) * 4, &A[(size_t)(m0 + r) * K + k0 + c4]);
        }
#pragma unroll
        for (int i = 0; i < 8; i++) {
            int g = tid + i * 256;
            int r = g >> 3, c4 = (g & 7) * 4;
            cp16(base + (WASZ + r * WPAD + c4) * 4, &B[(size_t)(n0 + r) * K + k0 + c4]);
        }
        CP_COMMIT();
    };

    load_stage(0, 0);

    for (int c = 0; c < nch; c++) {
        CP_WAIT(0);
        __syncthreads();
        if (c + 1 < nch) load_stage(c + 1, (c + 1) & 1);

        const float* sA = smf + (c & 1) * WSTG;
        const float* sB = sA + WASZ;

#pragma unroll
        for (int ks = 0; ks < 4; ks++) {
            const int k0 = ks * 8;
            uint32_t afr[4][4], bfr[8][2];
#pragma unroll
            for (int mf = 0; mf < 4; mf++) {
                int row = wm + mf * 16 + grp;
                afr[mf][0] = __float_as_uint(sA[row * WPAD + k0 + tg]);
                afr[mf][1] = __float_as_uint(sA[(row + 8) * WPAD + k0 + tg]);
                afr[mf][2] = __float_as_uint(sA[row * WPAD + k0 + tg + 4]);
                afr[mf][3] = __float_as_uint(sA[(row + 8) * WPAD + k0 + tg + 4]);
            }
#pragma unroll
            for (int nf = 0; nf < 8; nf++) {
                int col = wn + nf * 8 + grp;
                bfr[nf][0] = __float_as_uint(sB[col * WPAD + k0 + tg]);
                bfr[nf][1] = __float_as_uint(sB[col * WPAD + k0 + tg + 4]);
            }
#pragma unroll
            for (int mf = 0; mf < 4; mf++)
#pragma unroll
                for (int nf = 0; nf < 8; nf++)
                    mma_tf32(acc[mf][nf], afr[mf], bfr[nf], acc[mf][nf]);
        }
    }

#pragma unroll
    for (int mf = 0; mf < 4; mf++) {
#pragma unroll
        for (int nf = 0; nf < 8; nf++) {
            int row = m0 + wm + mf * 16 + grp;
            int col = n0 + wn + nf * 8 + tg * 2;
            float v0 = acc[mf][nf][0], v1 = acc[mf][nf][1];
            float v2 = acc[mf][nf][2], v3 = acc[mf][nf][3];
            if (mode == 2) {
                *(uint32_t*)&Ch[(size_t)row * N + col] = pack_h2(v0, v1);
                *(uint32_t*)&Ch[(size_t)(row + 8) * N + col] = pack_h2(v2, v3);
            } else {
                *(float2*)&C[(size_t)row * N + col] = make_float2(v0, v1);
                *(float2*)&C[(size_t)(row + 8) * N + col] = make_float2(v2, v3);
            }
        }
    }
}

// ===========================================================================
// Small GEMM: K proj (z==0) -> fp16 K [b,s,d]; V proj (z==1) -> fp16 V^T [b,d,s]
// ===========================================================================
#define BK   32
#define PAD  36

__global__ __launch_bounds__(256, 2) void gemm_kv(
    const float* __restrict__ A, const float* __restrict__ Bk,
    __half* __restrict__ Kh, int M, int N, int K,
    const float* __restrict__ Bv, __half* __restrict__ Vth)
{
    __shared__ uint32_t As[128 * PAD];
    __shared__ uint32_t Bs[128 * PAD];

    const float* B = (blockIdx.z == 1) ? Bv : Bk;

    const int tid  = threadIdx.x;
    const int wid  = tid >> 5;
    const int lane = tid & 31;
    const int grp  = lane >> 2;
    const int tg   = lane & 3;
    const int wm   = (wid & 1) * 64;
    const int wn   = (wid >> 1) * 32;
    const int m0 = blockIdx.y * 128;
    const int n0 = blockIdx.x * 128;

    const int ldr  = tid >> 3;
    const int ldc  = (tid & 7) * 4;

    float acc[4][4][4];
#pragma unroll
    for (int i = 0; i < 4; i++)
#pragma unroll
        for (int j = 0; j < 4; j++)
#pragma unroll
            for (int r = 0; r < 4; r++) acc[i][j][r] = 0.f;

    const int nchunks = K / BK;
    float4 pa[4], pb[4];

#pragma unroll
    for (int it = 0; it < 4; it++) {
        int r = ldr + it * 32;
        pa[it] = *(const float4*)&A[(size_t)(m0 + r) * K + ldc];
        pb[it] = *(const float4*)&B[(size_t)(n0 + r) * K + ldc];
    }

    for (int c = 0; c < nchunks; c++) {
#pragma unroll
        for (int it = 0; it < 4; it++) {
            int r = ldr + it * 32;
            As[r * PAD + ldc + 0] = cvt_tf32(pa[it].x);
            As[r * PAD + ldc + 1] = cvt_tf32(pa[it].y);
            As[r * PAD + ldc + 2] = cvt_tf32(pa[it].z);
            As[r * PAD + ldc + 3] = cvt_tf32(pa[it].w);
            Bs[r * PAD + ldc + 0] = cvt_tf32(pb[it].x);
            Bs[r * PAD + ldc + 1] = cvt_tf32(pb[it].y);
            Bs[r * PAD + ldc + 2] = cvt_tf32(pb[it].z);
            Bs[r * PAD + ldc + 3] = cvt_tf32(pb[it].w);
        }
        __syncthreads();

        if (c + 1 < nchunks) {
            const int k0 = (c + 1) * BK;
#pragma unroll
            for (int it = 0; it < 4; it++) {
                int r = ldr + it * 32;
                pa[it] = *(const float4*)&A[(size_t)(m0 + r) * K + k0 + ldc];
                pb[it] = *(const float4*)&B[(size_t)(n0 + r) * K + k0 + ldc];
            }
        }

#pragma unroll
        for (int ks = 0; ks < 4; ks++) {
            const int k0 = ks * 8;
            uint32_t afr[4][4], bfr[4][2];
#pragma unroll
            for (int mf = 0; mf < 4; mf++) {
                int row = wm + mf * 16 + grp;
                afr[mf][0] = As[row * PAD + k0 + tg];
                afr[mf][1] = As[(row + 8) * PAD + k0 + tg];
                afr[mf][2] = As[row * PAD + k0 + tg + 4];
                afr[mf][3] = As[(row + 8) * PAD + k0 + tg + 4];
            }
#pragma unroll
            for (int nf = 0; nf < 4; nf++) {
                int col = wn + nf * 8 + grp;
                bfr[nf][0] = Bs[col * PAD + k0 + tg];
                bfr[nf][1] = Bs[col * PAD + k0 + tg + 4];
            }
#pragma unroll
            for (int mf = 0; mf < 4; mf++)
#pragma unroll
                for (int nf = 0; nf < 4; nf++)
                    mma_tf32(acc[mf][nf], afr[mf], bfr[nf], acc[mf][nf]);
        }
        __syncthreads();
    }

#pragma unroll
    for (int mf = 0; mf < 4; mf++) {
#pragma unroll
        for (int nf = 0; nf < 4; nf++) {
            int row = m0 + wm + mf * 16 + grp;
            int col = n0 + wn + nf * 8 + tg * 2;
            float v0 = acc[mf][nf][0], v1 = acc[mf][nf][1];
            float v2 = acc[mf][nf][2], v3 = acc[mf][nf][3];
            if (blockIdx.z == 0) {
                *(uint32_t*)&Kh[(size_t)row * N + col] = pack_h2(v0, v1);
                *(uint32_t*)&Kh[(size_t)(row + 8) * N + col] = pack_h2(v2, v3);
            } else {
                int b = row >> 11, s = row & 2047;
                Vth[((size_t)b * HD + col) * SEQ + s]         = __float2half_rn(v0);
                Vth[((size_t)b * HD + col + 1) * SEQ + s]     = __float2half_rn(v1);
                Vth[((size_t)b * HD + col) * SEQ + s + 8]     = __float2half_rn(v2);
                Vth[((size_t)b * HD + col + 1) * SEQ + s + 8] = __float2half_rn(v3);
            }
        }
    }
}

// ===========================================================================
// fp16 tensor-core flash MQA. 8 warps, BQ=128, BKEY=64.
// K double-buffered, V^T single-buffered (load hidden behind next QK+softmax).
// m16n8k16: P A-frags are the thread's own S C-frags packed as half2.
// K row stride 272 B, V^T row stride 144 B (both ≡ 4 mod 32 words -> LDSM
// phases conflict-free).
// ===========================================================================
#define BQ     128
#define BKEY   64
#define KSTRB  272                    // 136 halves
#define VSTRB  144                    // 72 halves
#define OFFB_K0 0
#define OFFB_K1 (64 * KSTRB)          // 17408
#define OFFB_VT (2 * 64 * KSTRB)      // 34816
#define FLASH_SMEM (OFFB_VT + 128 * VSTRB)   // 53248 B

__global__ __launch_bounds__(256, 1) void flash_mqa_tc(
    const __half* __restrict__ Q, const __half* __restrict__ Kg,
    const __half* __restrict__ VTg, float* __restrict__ O)
{
    extern __shared__ char smc[];
    const uint32_t sb = smem_u32(smc);
    const int tid = threadIdx.x;
    const int wid = tid >> 5;
    const int lane = tid & 31;
    const int grp = lane >> 2;
    const int tg  = lane & 3;
    const int h = blockIdx.x & 15;
    const int b = blockIdx.x >> 4;
    const int q0 = blockIdx.y * BQ;
    const float scale = 0.08838834764831845f;   // 1/sqrt(128)

    const __half* kb  = Kg + (size_t)b * SEQ * HD;
    const __half* vtb = VTg + (size_t)b * HD * SEQ;
    const int nb = SEQ / BKEY;   // 32

    auto load_k = [&](int blk, uint32_t koffB) {
        const __half* src = kb + (size_t)blk * BKEY * HD;
#pragma unroll
        for (int it = 0; it < 4; it++) {
            int idx = tid + it * 256;            // 0..1023 granules (16B)
            int r = idx >> 4, c16 = idx & 15;    // 64 rows x 16 granules
            cp16(sb + koffB + r * KSTRB + c16 * 16, src + (size_t)r * HD + c16 * 8);
        }
    };
    auto load_vt = [&](int blk) {
        const __half* src = vtb + blk * BKEY;
#pragma unroll
        for (int it = 0; it < 4; it++) {
            int idx = tid + it * 256;            // 0..1023 granules
            int r = idx >> 3, c16 = idx & 7;     // 128 rows x 8 granules
            cp16(sb + OFFB_VT + r * VSTRB + c16 * 16, src + (size_t)r * SEQ + c16 * 8);
        }
    };

    // Q fragments (fp16, m16n8k16 A layout): 8 k-steps of 16
    uint32_t qf[8][4];
    {
        const __half* qb = Q + (size_t)(b * SEQ + q0 + wid * 16) * HID + h * HD;
#pragma unroll
        for (int ks = 0; ks < 8; ks++) {
            int col = ks * 16 + 2 * tg;
            qf[ks][0] = *(const uint32_t*)&qb[(size_t)grp * HID + col];
            qf[ks][1] = *(const uint32_t*)&qb[(size_t)(grp + 8) * HID + col];
            qf[ks][2] = *(const uint32_t*)&qb[(size_t)grp * HID + col + 8];
            qf[ks][3] = *(const uint32_t*)&qb[(size_t)(grp + 8) * HID + col + 8];
        }
    }

    float o[16][4];
#pragma unroll
    for (int i = 0; i < 16; i++)
#pragma unroll
        for (int j = 0; j < 4; j++) o[i][j] = 0.f;
    float m0r = -1e30f, m1r = -1e30f, l0 = 0.f, l1 = 0.f;

    load_k(0, OFFB_K0); load_vt(0); CP_COMMIT();
    load_k(1, OFFB_K1); CP_COMMIT();

    // LDSM lane geometry: rows within 16-row pair, 16B k-chunk select
    const int lrow8  = ((lane >> 4) & 1) * 8 + (lane & 7);
    const int lcol16 = (lane >> 3) & 1;

    for (int blk = 0; blk < nb; blk++) {
        CP_WAIT(1);
        __syncthreads();

        const uint32_t kOffB = sb + ((blk & 1) ? OFFB_K1 : OFFB_K0);
        const uint32_t vOffB = sb + OFFB_VT;

        // ---- S = Q * K^T : 8 k-steps(16) x 8 n-tiles ----
        float s[8][4];
#pragma unroll
        for (int nt = 0; nt < 8; nt++)
#pragma unroll
            for (int j = 0; j < 4; j++) s[nt][j] = 0.f;

#pragma unroll
        for (int ks = 0; ks < 8; ks++) {
#pragma unroll
            for (int p = 0; p < 4; p++) {      // pairs of n-tiles (16 keys)
                uint32_t b0, b1, b2, b3;
                uint32_t addr = kOffB +
                    (uint32_t)((p * 16 + lrow8) * KSTRB + ks * 32 + lcol16 * 16);
                ldsm4(b0, b1, b2, b3, addr);
                uint32_t bf0[2] = {b0, b1}, bf1[2] = {b2, b3};
                mma_f16(s[2 * p],     qf[ks], bf0, s[2 * p]);
                mma_f16(s[2 * p + 1], qf[ks], bf1, s[2 * p + 1]);
            }
        }

        // ---- online softmax; P packed to half2 (own C-frags = A-frags) ----
        float ml0 = -1e30f, ml1 = -1e30f;
#pragma unroll
        for (int nt = 0; nt < 8; nt++) {
            ml0 = fmaxf(ml0, fmaxf(s[nt][0], s[nt][1]));
            ml1 = fmaxf(ml1, fmaxf(s[nt][2], s[nt][3]));
        }
        ml0 *= scale; ml1 *= scale;
#pragma unroll
        for (int off = 1; off < 4; off <<= 1) {
            ml0 = fmaxf(ml0, __shfl_xor_sync(0xffffffffu, ml0, off));
            ml1 = fmaxf(ml1, __shfl_xor_sync(0xffffffffu, ml1, off));
        }
        const float mn0 = fmaxf(m0r, ml0);
        const float mn1 = fmaxf(m1r, ml1);
        const float a0 = __expf(m0r - mn0);
        const float a1 = __expf(m1r - mn1);
        float sum0 = 0.f, sum1 = 0.f;
        uint32_t pf[8][2];
#pragma unroll
        for (int nt = 0; nt < 8; nt++) {
            float p00 = __expf(s[nt][0] * scale - mn0);
            float p01 = __expf(s[nt][1] * scale - mn0);
            float p10 = __expf(s[nt][2] * scale - mn1);
            float p11 = __expf(s[nt][3] * scale - mn1);
            sum0 += p00 + p01;
            sum1 += p10 + p11;
            pf[nt][0] = pack_h2(p00, p01);
            pf[nt][1] = pack_h2(p10, p11);
        }
#pragma unroll
        for (int off = 1; off < 4; off <<= 1) {
            sum0 += __shfl_xor_sync(0xffffffffu, sum0, off);
            sum1 += __shfl_xor_sync(0xffffffffu, sum1, off);
        }
        l0 = l0 * a0 + sum0;
        l1 = l1 * a1 + sum1;
        m0r = mn0; m1r = mn1;
#pragma unroll
        for (int nt = 0; nt < 16; nt++) {
            o[nt][0] *= a0; o[nt][1] *= a0;
            o[nt][2] *= a1; o[nt][3] *= a1;
        }

        // ---- O += P * V : 4 k-steps(16 keys) x 16 d-tiles ----
#pragma unroll
        for (int ks2 = 0; ks2 < 4; ks2++) {
            uint32_t af[4] = { pf[2 * ks2][0], pf[2 * ks2][1],
                               pf[2 * ks2 + 1][0], pf[2 * ks2 + 1][1] };
#pragma unroll
            for (int p = 0; p < 8; p++) {      // pairs of d-tiles
                uint32_t b0, b1, b2, b3;
                uint32_t addr = vOffB +
                    (uint32_t)((p * 16 + lrow8) * VSTRB + ks2 * 32 + lcol16 * 16);
                ldsm4(b0, b1, b2, b3, addr);
                uint32_t bf0[2] = {b0, b1}, bf1[2] = {b2, b3};
                mma_f16(o[2 * p],     af, bf0, o[2 * p]);
                mma_f16(o[2 * p + 1], af, bf1, o[2 * p + 1]);
            }
        }
        __syncthreads();

        if (blk + 1 < nb) load_vt(blk + 1);
        CP_COMMIT();
        if (blk + 2 < nb) load_k(blk + 2, (blk & 1) ? OFFB_K1 : OFFB_K0);
        CP_COMMIT();
    }

    // ---- epilogue: tf32-rounded fp32 for the out-projection cp.async path ----
    const float inv0 = 1.f / l0;
    const float inv1 = 1.f / l1;
    float* ob = O + (size_t)(b * SEQ + q0 + wid * 16) * HID + h * HD;
#pragma unroll
    for (int nt = 0; nt < 16; nt++) {
        int c = nt * 8 + 2 * tg;
        float v0 = __uint_as_float(cvt_tf32(o[nt][0] * inv0));
        float v1 = __uint_as_float(cvt_tf32(o[nt][1] * inv0));
        float v2 = __uint_as_float(cvt_tf32(o[nt][2] * inv1));
        float v3 = __uint_as_float(cvt_tf32(o[nt][3] * inv1));
        *(float2*)&ob[(size_t)grp * HID + c] = make_float2(v0, v1);
        *(float2*)&ob[(size_t)(grp + 8) * HID + c] = make_float2(v2, v3);
    }
}

// ===========================================================================
extern "C" void kernel_launch(void* const* d_in, const int* in_sizes, int n_in,
                              void* d_out, int out_size)
{
    const float* x  = (const float*)d_in[0];
    const float* wq = (const float*)d_in[1];
    const float* wk = (const float*)d_in[2];
    const float* wv = (const float*)d_in[3];
    const float* wo = (const float*)d_in[4];
    float* out = (float*)d_out;

    __half *qh, *kh, *vth;
    float *o, *xr, *wqr, *wor;
    cudaGetSymbolAddress((void**)&qh, g_qh);
    cudaGetSymbolAddress((void**)&kh, g_kh);
    cudaGetSymbolAddress((void**)&vth, g_vth);
    cudaGetSymbolAddress((void**)&o, g_o);
    cudaGetSymbolAddress((void**)&xr, g_x);
    cudaGetSymbolAddress((void**)&wqr, g_wq);
    cudaGetSymbolAddress((void**)&wor, g_wo);

    cudaFuncSetAttribute(flash_mqa_tc,
                         cudaFuncAttributeMaxDynamicSharedMemorySize, FLASH_SMEM);
    cudaFuncSetAttribute(gemm_wide,
                         cudaFuncAttributeMaxDynamicSharedMemorySize, WSMEM);

    // Round x, w_q, w_out to tf32
    round3_tf32<<<2048, 256>>>(x, xr, MROWS * HID / 4,
                               wq, wqr, HID * HID / 4,
                               wo, wor, HID * HID / 4);

    // Q projection -> fp16
    gemm_wide<<<dim3(HID / 256, MROWS / 128), 256, WSMEM>>>(
        xr, wqr, nullptr, qh, MROWS, HID, HID, 2);

    // K (fp16) and V^T (fp16) projections fused
    gemm_kv<<<dim3(HD / 128, MROWS / 128, 2), 256>>>(
        x, wk, kh, MROWS, HD, HID, wv, vth);

    // fp16 tensor-core flash attention
    flash_mqa_tc<<<dim3(BATCH * NH, SEQ / BQ), 256, FLASH_SMEM>>>(qh, kh, vth, o);

    // Output projection (fp32 out)
    gemm_wide<<<dim3(HID / 256, MROWS / 128), 256, WSMEM>>>(
        o, wor, out, nullptr, MROWS, HID, HID, 0);
}

// round 16
// speedup vs baseline: 1.8835x; 1.3048x over previous
#include <cuda_runtime.h>
#include <cuda_fp16.h>
#include <cstdint>

#define HID   2048
#define HD    128
#define NH    16
#define BATCH 2
#define SEQ   2048
#define MROWS (BATCH*SEQ)   // 4096

// Scratch (no allocation allowed -> __device__ globals)
__device__ __half g_xh[(size_t)MROWS * HID];        // x fp16
__device__ __half g_wqh[(size_t)HID * HID];         // w_q fp16
__device__ __half g_woh[(size_t)HID * HID];         // w_out fp16
__device__ __half g_qh[(size_t)MROWS * HID];        // Q fp16
__device__ __half g_kh[(size_t)MROWS * HD];         // K fp16 [b,s,d]
__device__ __half g_vth[(size_t)BATCH * HD * SEQ];  // V^T fp16 [b,d,s]
__device__ __half g_oh[(size_t)MROWS * HID];        // attention out fp16

__device__ __forceinline__ uint32_t cvt_tf32(float x) {
    uint32_t r; asm("cvt.rna.tf32.f32 %0, %1;" : "=r"(r) : "f"(x)); return r;
}

__device__ __forceinline__ void mma_tf32(float* d, const uint32_t* a,
                                         const uint32_t* b, const float* c) {
    asm volatile(
        "mma.sync.aligned.m16n8k8.row.col.f32.tf32.tf32.f32 "
        "{%0,%1,%2,%3}, {%4,%5,%6,%7}, {%8,%9}, {%10,%11,%12,%13};"
        : "=f"(d[0]), "=f"(d[1]), "=f"(d[2]), "=f"(d[3])
        : "r"(a[0]), "r"(a[1]), "r"(a[2]), "r"(a[3]),
          "r"(b[0]), "r"(b[1]),
          "f"(c[0]), "f"(c[1]), "f"(c[2]), "f"(c[3]));
}

__device__ __forceinline__ void mma_f16(float* d, const uint32_t* a,
                                        const uint32_t* b, const float* c) {
    asm volatile(
        "mma.sync.aligned.m16n8k16.row.col.f32.f16.f16.f32 "
        "{%0,%1,%2,%3}, {%4,%5,%6,%7}, {%8,%9}, {%10,%11,%12,%13};"
        : "=f"(d[0]), "=f"(d[1]), "=f"(d[2]), "=f"(d[3])
        : "r"(a[0]), "r"(a[1]), "r"(a[2]), "r"(a[3]),
          "r"(b[0]), "r"(b[1]),
          "f"(c[0]), "f"(c[1]), "f"(c[2]), "f"(c[3]));
}

__device__ __forceinline__ void ldsm4(uint32_t& r0, uint32_t& r1,
                                      uint32_t& r2, uint32_t& r3, uint32_t addr) {
    asm volatile("ldmatrix.sync.aligned.m8n8.x4.shared.b16 {%0,%1,%2,%3}, [%4];"
                 : "=r"(r0), "=r"(r1), "=r"(r2), "=r"(r3) : "r"(addr));
}

__device__ __forceinline__ void cp16(uint32_t dst, const void* src) {
    asm volatile("cp.async.ca.shared.global [%0], [%1], 16;" :: "r"(dst), "l"(src));
}
#define CP_COMMIT() asm volatile("cp.async.commit_group;" ::: "memory")
#define CP_WAIT(n)  asm volatile("cp.async.wait_group %0;" :: "n"(n) : "memory")

__device__ __forceinline__ uint32_t smem_u32(const void* p) {
    uint32_t a;
    asm("{ .reg .u64 t; cvta.to.shared.u64 t, %1; cvt.u32.u64 %0, t; }"
        : "=r"(a) : "l"(p));
    return a;
}

__device__ __forceinline__ uint32_t pack_h2(float lo, float hi) {
    __half2 h = __floats2half2_rn(lo, hi);
    return *reinterpret_cast<uint32_t*>(&h);
}

// ===========================================================================
// Pre-pass: convert x, w_q, w_out to fp16 (RN)
// ===========================================================================
__global__ void conv3_f16(const float* __restrict__ a, __half* __restrict__ ao, int na4,
                          const float* __restrict__ b, __half* __restrict__ bo, int nb4,
                          const float* __restrict__ c, __half* __restrict__ co, int nc4)
{
    int total = na4 + nb4 + nc4;
    for (int i = blockIdx.x * blockDim.x + threadIdx.x; i < total;
         i += gridDim.x * blockDim.x) {
        const float4* src; __half* dst; int j = i;
        if (j < na4) { src = (const float4*)a; dst = ao; }
        else if ((j -= na4) < nb4) { src = (const float4*)b; dst = bo; }
        else { j -= nb4; src = (const float4*)c; dst = co; }
        float4 v = src[j];
        uint32_t lo = pack_h2(v.x, v.y);
        uint32_t hi = pack_h2(v.z, v.w);
        *(uint2*)&dst[(size_t)j * 4] = make_uint2(lo, hi);
    }
}

// ===========================================================================
// fp16 wide GEMM: C[M,N] = A[M,K] * B[N,K]^T. 128x256 CTA, 8 warps of 64x64,
// BK=64, cp.async double-buffered, all fragments via ldmatrix.x4.
// Row stride 144 B (proven conflict-free LDSM pattern). mode 2: fp16 out.
// ===========================================================================
#define FSTR   144                      // bytes per 64-half row (128 data + 16 pad)
#define FASZ   (128 * FSTR)             // 18432
#define FBSZ   (256 * FSTR)             // 36864
#define FSTG   (FASZ + FBSZ)            // 55296
#define FSMEM  (2 * FSTG)               // 110592

__global__ __launch_bounds__(256, 1) void gemm_wide_f16(
    const __half* __restrict__ A, const __half* __restrict__ B,
    float* __restrict__ C, __half* __restrict__ Ch,
    int M, int N, int K, int mode)
{
    extern __shared__ char smc[];
    const uint32_t sb = smem_u32(smc);
    const int tid  = threadIdx.x;
    const int wid  = tid >> 5;
    const int lane = tid & 31;
    const int grp  = lane >> 2;
    const int tg   = lane & 3;
    const int wm   = (wid & 1) * 64;
    const int wn   = (wid >> 1) * 64;
    const int m0 = blockIdx.y * 128;
    const int n0 = blockIdx.x * 256;

    float acc[4][8][4];
#pragma unroll
    for (int i = 0; i < 4; i++)
#pragma unroll
        for (int j = 0; j < 8; j++)
#pragma unroll
            for (int r = 0; r < 4; r++) acc[i][j][r] = 0.f;

    const int nch = K / 64;   // 32

    auto load_stage = [&](int c, int buf) {
        const int k0 = c * 64;
        const uint32_t base = sb + buf * FSTG;
#pragma unroll
        for (int i = 0; i < 4; i++) {            // A: 1024 granules
            int g = tid + i * 256;
            int r = g >> 3, c16 = g & 7;
            cp16(base + r * FSTR + c16 * 16, A + (size_t)(m0 + r) * K + k0 + c16 * 8);
        }
#pragma unroll
        for (int i = 0; i < 8; i++) {            // B: 2048 granules
            int g = tid + i * 256;
            int r = g >> 3, c16 = g & 7;
            cp16(base + FASZ + r * FSTR + c16 * 16,
                 B + (size_t)(n0 + r) * K + k0 + c16 * 8);
        }
        CP_COMMIT();
    };

    load_stage(0, 0);

    // LDSM geometry (same as flash): lrow8 row-in-16, lcol16 k-chunk half
    const int lrow8  = ((lane >> 4) & 1) * 8 + (lane & 7);
    const int lcol16 = (lane >> 3) & 1;

    for (int c = 0; c < nch; c++) {
        CP_WAIT(0);
        __syncthreads();
        if (c + 1 < nch) load_stage(c + 1, (c + 1) & 1);

        const uint32_t aB = sb + (c & 1) * FSTG;
        const uint32_t bB = aB + FASZ;

#pragma unroll
        for (int ks = 0; ks < 4; ks++) {
            uint32_t af[4][4];
#pragma unroll
            for (int mf = 0; mf < 4; mf++) {
                uint32_t r0, r1, r2, r3;
                ldsm4(r0, r1, r2, r3,
                      aB + (uint32_t)((wm + mf * 16 + lrow8) * FSTR
                                      + ks * 32 + lcol16 * 16));
                af[mf][0] = r0; af[mf][1] = r2; af[mf][2] = r1; af[mf][3] = r3;
            }
#pragma unroll
            for (int p = 0; p < 4; p++) {
                uint32_t b0, b1, b2, b3;
                ldsm4(b0, b1, b2, b3,
                      bB + (uint32_t)((wn + p * 16 + lrow8) * FSTR
                                      + ks * 32 + lcol16 * 16));
                uint32_t bf0[2] = {b0, b1}, bf1[2] = {b2, b3};
#pragma unroll
                for (int mf = 0; mf < 4; mf++) {
                    mma_f16(acc[mf][2 * p],     af[mf], bf0, acc[mf][2 * p]);
                    mma_f16(acc[mf][2 * p + 1], af[mf], bf1, acc[mf][2 * p + 1]);
                }
            }
        }
    }

#pragma unroll
    for (int mf = 0; mf < 4; mf++) {
#pragma unroll
        for (int nf = 0; nf < 8; nf++) {
            int row = m0 + wm + mf * 16 + grp;
            int col = n0 + wn + nf * 8 + tg * 2;
            float v0 = acc[mf][nf][0], v1 = acc[mf][nf][1];
            float v2 = acc[mf][nf][2], v3 = acc[mf][nf][3];
            if (mode == 2) {
                *(uint32_t*)&Ch[(size_t)row * N + col] = pack_h2(v0, v1);
                *(uint32_t*)&Ch[(size_t)(row + 8) * N + col] = pack_h2(v2, v3);
            } else {
                *(float2*)&C[(size_t)row * N + col] = make_float2(v0, v1);
                *(float2*)&C[(size_t)(row + 8) * N + col] = make_float2(v2, v3);
            }
        }
    }
}

// ===========================================================================
// Small GEMM (tf32): K proj (z==0) -> fp16 K [b,s,d]; V proj (z==1) -> fp16 V^T
// ===========================================================================
#define BK   32
#define PAD  36

__global__ __launch_bounds__(256, 2) void gemm_kv(
    const float* __restrict__ A, const float* __restrict__ Bk,
    __half* __restrict__ Kh, int M, int N, int K,
    const float* __restrict__ Bv, __half* __restrict__ Vth)
{
    __shared__ uint32_t As[128 * PAD];
    __shared__ uint32_t Bs[128 * PAD];

    const float* B = (blockIdx.z == 1) ? Bv : Bk;

    const int tid  = threadIdx.x;
    const int wid  = tid >> 5;
    const int lane = tid & 31;
    const int grp  = lane >> 2;
    const int tg   = lane & 3;
    const int wm   = (wid & 1) * 64;
    const int wn   = (wid >> 1) * 32;
    const int m0 = blockIdx.y * 128;
    const int n0 = blockIdx.x * 128;

    const int ldr  = tid >> 3;
    const int ldc  = (tid & 7) * 4;

    float acc[4][4][4];
#pragma unroll
    for (int i = 0; i < 4; i++)
#pragma unroll
        for (int j = 0; j < 4; j++)
#pragma unroll
            for (int r = 0; r < 4; r++) acc[i][j][r] = 0.f;

    const int nchunks = K / BK;
    float4 pa[4], pb[4];

#pragma unroll
    for (int it = 0; it < 4; it++) {
        int r = ldr + it * 32;
        pa[it] = *(const float4*)&A[(size_t)(m0 + r) * K + ldc];
        pb[it] = *(const float4*)&B[(size_t)(n0 + r) * K + ldc];
    }

    for (int c = 0; c < nchunks; c++) {
#pragma unroll
        for (int it = 0; it < 4; it++) {
            int r = ldr + it * 32;
            As[r * PAD + ldc + 0] = cvt_tf32(pa[it].x);
            As[r * PAD + ldc + 1] = cvt_tf32(pa[it].y);
            As[r * PAD + ldc + 2] = cvt_tf32(pa[it].z);
            As[r * PAD + ldc + 3] = cvt_tf32(pa[it].w);
            Bs[r * PAD + ldc + 0] = cvt_tf32(pb[it].x);
            Bs[r * PAD + ldc + 1] = cvt_tf32(pb[it].y);
            Bs[r * PAD + ldc + 2] = cvt_tf32(pb[it].z);
            Bs[r * PAD + ldc + 3] = cvt_tf32(pb[it].w);
        }
        __syncthreads();

        if (c + 1 < nchunks) {
            const int k0 = (c + 1) * BK;
#pragma unroll
            for (int it = 0; it < 4; it++) {
                int r = ldr + it * 32;
                pa[it] = *(const float4*)&A[(size_t)(m0 + r) * K + k0 + ldc];
                pb[it] = *(const float4*)&B[(size_t)(n0 + r) * K + k0 + ldc];
            }
        }

#pragma unroll
        for (int ks = 0; ks < 4; ks++) {
            const int k0 = ks * 8;
            uint32_t afr[4][4], bfr[4][2];
#pragma unroll
            for (int mf = 0; mf < 4; mf++) {
                int row = wm + mf * 16 + grp;
                afr[mf][0] = As[row * PAD + k0 + tg];
                afr[mf][1] = As[(row + 8) * PAD + k0 + tg];
                afr[mf][2] = As[row * PAD + k0 + tg + 4];
                afr[mf][3] = As[(row + 8) * PAD + k0 + tg + 4];
            }
#pragma unroll
            for (int nf = 0; nf < 4; nf++) {
                int col = wn + nf * 8 + grp;
                bfr[nf][0] = Bs[col * PAD + k0 + tg];
                bfr[nf][1] = Bs[col * PAD + k0 + tg + 4];
            }
#pragma unroll
            for (int mf = 0; mf < 4; mf++)
#pragma unroll
                for (int nf = 0; nf < 4; nf++)
                    mma_tf32(acc[mf][nf], afr[mf], bfr[nf], acc[mf][nf]);
        }
        __syncthreads();
    }

#pragma unroll
    for (int mf = 0; mf < 4; mf++) {
#pragma unroll
        for (int nf = 0; nf < 4; nf++) {
            int row = m0 + wm + mf * 16 + grp;
            int col = n0 + wn + nf * 8 + tg * 2;
            float v0 = acc[mf][nf][0], v1 = acc[mf][nf][1];
            float v2 = acc[mf][nf][2], v3 = acc[mf][nf][3];
            if (blockIdx.z == 0) {
                *(uint32_t*)&Kh[(size_t)row * N + col] = pack_h2(v0, v1);
                *(uint32_t*)&Kh[(size_t)(row + 8) * N + col] = pack_h2(v2, v3);
            } else {
                int b = row >> 11, s = row & 2047;
                Vth[((size_t)b * HD + col) * SEQ + s]         = __float2half_rn(v0);
                Vth[((size_t)b * HD + col + 1) * SEQ + s]     = __float2half_rn(v1);
                Vth[((size_t)b * HD + col) * SEQ + s + 8]     = __float2half_rn(v2);
                Vth[((size_t)b * HD + col + 1) * SEQ + s + 8] = __float2half_rn(v3);
            }
        }
    }
}

// ===========================================================================
// fp16 tensor-core flash MQA (unchanged structure; epilogue writes fp16 O)
// ===========================================================================
#define BQ     128
#define BKEY   64
#define KSTRB  272
#define VSTRB  144
#define OFFB_K0 0
#define OFFB_K1 (64 * KSTRB)
#define OFFB_VT (2 * 64 * KSTRB)
#define FLASH_SMEM (OFFB_VT + 128 * VSTRB)   // 53248 B

__global__ __launch_bounds__(256, 1) void flash_mqa_tc(
    const __half* __restrict__ Q, const __half* __restrict__ Kg,
    const __half* __restrict__ VTg, __half* __restrict__ O)
{
    extern __shared__ char smc[];
    const uint32_t sb = smem_u32(smc);
    const int tid = threadIdx.x;
    const int wid = tid >> 5;
    const int lane = tid & 31;
    const int grp = lane >> 2;
    const int tg  = lane & 3;
    const int h = blockIdx.x & 15;
    const int b = blockIdx.x >> 4;
    const int q0 = blockIdx.y * BQ;
    const float scale = 0.08838834764831845f;   // 1/sqrt(128)

    const __half* kb  = Kg + (size_t)b * SEQ * HD;
    const __half* vtb = VTg + (size_t)b * HD * SEQ;
    const int nb = SEQ / BKEY;   // 32

    auto load_k = [&](int blk, uint32_t koffB) {
        const __half* src = kb + (size_t)blk * BKEY * HD;
#pragma unroll
        for (int it = 0; it < 4; it++) {
            int idx = tid + it * 256;
            int r = idx >> 4, c16 = idx & 15;
            cp16(sb + koffB + r * KSTRB + c16 * 16, src + (size_t)r * HD + c16 * 8);
        }
    };
    auto load_vt = [&](int blk) {
        const __half* src = vtb + blk * BKEY;
#pragma unroll
        for (int it = 0; it < 4; it++) {
            int idx = tid + it * 256;
            int r = idx >> 3, c16 = idx & 7;
            cp16(sb + OFFB_VT + r * VSTRB + c16 * 16, src + (size_t)r * SEQ + c16 * 8);
        }
    };

    uint32_t qf[8][4];
    {
        const __half* qb = Q + (size_t)(b * SEQ + q0 + wid * 16) * HID + h * HD;
#pragma unroll
        for (int ks = 0; ks < 8; ks++) {
            int col = ks * 16 + 2 * tg;
            qf[ks][0] = *(const uint32_t*)&qb[(size_t)grp * HID + col];
            qf[ks][1] = *(const uint32_t*)&qb[(size_t)(grp + 8) * HID + col];
            qf[ks][2] = *(const uint32_t*)&qb[(size_t)grp * HID + col + 8];
            qf[ks][3] = *(const uint32_t*)&qb[(size_t)(grp + 8) * HID + col + 8];
        }
    }

    float o[16][4];
#pragma unroll
    for (int i = 0; i < 16; i++)
#pragma unroll
        for (int j = 0; j < 4; j++) o[i][j] = 0.f;
    float m0r = -1e30f, m1r = -1e30f, l0 = 0.f, l1 = 0.f;

    load_k(0, OFFB_K0); load_vt(0); CP_COMMIT();
    load_k(1, OFFB_K1); CP_COMMIT();

    const int lrow8  = ((lane >> 4) & 1) * 8 + (lane & 7);
    const int lcol16 = (lane >> 3) & 1;

    for (int blk = 0; blk < nb; blk++) {
        CP_WAIT(1);
        __syncthreads();

        const uint32_t kOffB = sb + ((blk & 1) ? OFFB_K1 : OFFB_K0);
        const uint32_t vOffB = sb + OFFB_VT;

        float s[8][4];
#pragma unroll
        for (int nt = 0; nt < 8; nt++)
#pragma unroll
            for (int j = 0; j < 4; j++) s[nt][j] = 0.f;

#pragma unroll
        for (int ks = 0; ks < 8; ks++) {
#pragma unroll
            for (int p = 0; p < 4; p++) {
                uint32_t b0, b1, b2, b3;
                uint32_t addr = kOffB +
                    (uint32_t)((p * 16 + lrow8) * KSTRB + ks * 32 + lcol16 * 16);
                ldsm4(b0, b1, b2, b3, addr);
                uint32_t bf0[2] = {b0, b1}, bf1[2] = {b2, b3};
                mma_f16(s[2 * p],     qf[ks], bf0, s[2 * p]);
                mma_f16(s[2 * p + 1], qf[ks], bf1, s[2 * p + 1]);
            }
        }

        float ml0 = -1e30f, ml1 = -1e30f;
#pragma unroll
        for (int nt = 0; nt < 8; nt++) {
            ml0 = fmaxf(ml0, fmaxf(s[nt][0], s[nt][1]));
            ml1 = fmaxf(ml1, fmaxf(s[nt][2], s[nt][3]));
        }
        ml0 *= scale; ml1 *= scale;
#pragma unroll
        for (int off = 1; off < 4; off <<= 1) {
            ml0 = fmaxf(ml0, __shfl_xor_sync(0xffffffffu, ml0, off));
            ml1 = fmaxf(ml1, __shfl_xor_sync(0xffffffffu, ml1, off));
        }
        const float mn0 = fmaxf(m0r, ml0);
        const float mn1 = fmaxf(m1r, ml1);
        const float a0 = __expf(m0r - mn0);
        const float a1 = __expf(m1r - mn1);
        float sum0 = 0.f, sum1 = 0.f;
        uint32_t pf[8][2];
#pragma unroll
        for (int nt = 0; nt < 8; nt++) {
            float p00 = __expf(s[nt][0] * scale - mn0);
            float p01 = __expf(s[nt][1] * scale - mn0);
            float p10 = __expf(s[nt][2] * scale - mn1);
            float p11 = __expf(s[nt][3] * scale - mn1);
            sum0 += p00 + p01;
            sum1 += p10 + p11;
            pf[nt][0] = pack_h2(p00, p01);
            pf[nt][1] = pack_h2(p10, p11);
        }
#pragma unroll
        for (int off = 1; off < 4; off <<= 1) {
            sum0 += __shfl_xor_sync(0xffffffffu, sum0, off);
            sum1 += __shfl_xor_sync(0xffffffffu, sum1, off);
        }
        l0 = l0 * a0 + sum0;
        l1 = l1 * a1 + sum1;
        m0r = mn0; m1r = mn1;
#pragma unroll
        for (int nt = 0; nt < 16; nt++) {
            o[nt][0] *= a0; o[nt][1] *= a0;
            o[nt][2] *= a1; o[nt][3] *= a1;
        }

#pragma unroll
        for (int ks2 = 0; ks2 < 4; ks2++) {
            uint32_t af[4] = { pf[2 * ks2][0], pf[2 * ks2][1],
                               pf[2 * ks2 + 1][0], pf[2 * ks2 + 1][1] };
#pragma unroll
            for (int p = 0; p < 8; p++) {
                uint32_t b0, b1, b2, b3;
                uint32_t addr = vOffB +
                    (uint32_t)((p * 16 + lrow8) * VSTRB + ks2 * 32 + lcol16 * 16);
                ldsm4(b0, b1, b2, b3, addr);
                uint32_t bf0[2] = {b0, b1}, bf1[2] = {b2, b3};
                mma_f16(o[2 * p],     af, bf0, o[2 * p]);
                mma_f16(o[2 * p + 1], af, bf1, o[2 * p + 1]);
            }
        }
        __syncthreads();

        if (blk + 1 < nb) load_vt(blk + 1);
        CP_COMMIT();
        if (blk + 2 < nb) load_k(blk + 2, (blk & 1) ? OFFB_K1 : OFFB_K0);
        CP_COMMIT();
    }

    // ---- epilogue: fp16 O for the fp16 out-projection ----
    const float inv0 = 1.f / l0;
    const float inv1 = 1.f / l1;
    __half* ob = O + (size_t)(b * SEQ + q0 + wid * 16) * HID + h * HD;
#pragma unroll
    for (int nt = 0; nt < 16; nt++) {
        int c = nt * 8 + 2 * tg;
        *(uint32_t*)&ob[(size_t)grp * HID + c] =
            pack_h2(o[nt][0] * inv0, o[nt][1] * inv0);
        *(uint32_t*)&ob[(size_t)(grp + 8) * HID + c] =
            pack_h2(o[nt][2] * inv1, o[nt][3] * inv1);
    }
}

// ===========================================================================
extern "C" void kernel_launch(void* const* d_in, const int* in_sizes, int n_in,
                              void* d_out, int out_size)
{
    const float* x  = (const float*)d_in[0];
    const float* wq = (const float*)d_in[1];
    const float* wk = (const float*)d_in[2];
    const float* wv = (const float*)d_in[3];
    const float* wo = (const float*)d_in[4];
    float* out = (float*)d_out;

    __half *xh, *wqh, *woh, *qh, *kh, *vth, *oh;
    cudaGetSymbolAddress((void**)&xh, g_xh);
    cudaGetSymbolAddress((void**)&wqh, g_wqh);
    cudaGetSymbolAddress((void**)&woh, g_woh);
    cudaGetSymbolAddress((void**)&qh, g_qh);
    cudaGetSymbolAddress((void**)&kh, g_kh);
    cudaGetSymbolAddress((void**)&vth, g_vth);
    cudaGetSymbolAddress((void**)&oh, g_oh);

    cudaFuncSetAttribute(flash_mqa_tc,
                         cudaFuncAttributeMaxDynamicSharedMemorySize, FLASH_SMEM);
    cudaFuncSetAttribute(gemm_wide_f16,
                         cudaFuncAttributeMaxDynamicSharedMemorySize, FSMEM);

    // Convert x, w_q, w_out to fp16
    conv3_f16<<<2048, 256>>>(x, xh, MROWS * HID / 4,
                             wq, wqh, HID * HID / 4,
                             wo, woh, HID * HID / 4);

    // Q projection (fp16 GEMM -> fp16 out)
    gemm_wide_f16<<<dim3(HID / 256, MROWS / 128), 256, FSMEM>>>(
        xh, wqh, nullptr, qh, MROWS, HID, HID, 2);

    // K (fp16) and V^T (fp16) projections fused (tf32 path from fp32 x)
    gemm_kv<<<dim3(HD / 128, MROWS / 128, 2), 256>>>(
        x, wk, kh, MROWS, HD, HID, wv, vth);

    // fp16 tensor-core flash attention (fp16 O out)
    flash_mqa_tc<<<dim3(BATCH * NH, SEQ / BQ), 256, FLASH_SMEM>>>(qh, kh, vth, oh);

    // Output projection (fp16 GEMM -> fp32 out)
    gemm_wide_f16<<<dim3(HID / 256, MROWS / 128), 256, FSMEM>>>(
        oh, woh, out, nullptr, MROWS, HID, HID, 0);
}